// round 7
// baseline (speedup 1.0000x reference)
#include <cuda_runtime.h>
#include <math_constants.h>

// CrumbReconstructor: per 8-float block of x, argmin over 256 codebook rows of
// squared L2, emit the winning row.
//
// score(j) = ||m_j||^2 - 2*k.m_j   (||k||^2 dropped: uniform in j).
//
// f32x2 pairs TWO CODES (j, j+1) per lane-pair. Keys dup-packed once at load;
// codebook smem pair-interleaved (4x LDS.128 + 1x LDS.64 per code pair);
// 8 FFMA2 yield both codes' final scores (seed = (mm_j, mm_j+1)).
//
// R6: latency-clean argmin. R5 showed issue stuck at 63% independent of
// occupancy: the `if (m<best)` guarded updates make a 13-cyc loop-carried
// FSETP->@p chain (pred-as-guard = 13 cyc; pred-as-data = 4). Replace with
// separate even/odd running minima updated via FMNMX + SEL(pred-as-data):
// all carried chains become lat-4.

#define MBLK   8
#define NCODES 256
#define NJP    (NCODES / 2)   // 128 code pairs
#define TPB    128
#define KPT    4              // key-blocks per thread

typedef unsigned long long u64;

__device__ __forceinline__ u64 pack2(float lo, float hi) {
    u64 r; asm("mov.b64 %0, {%1, %2};" : "=l"(r) : "f"(lo), "f"(hi)); return r;
}
__device__ __forceinline__ void unpack2(u64 v, float& lo, float& hi) {
    asm("mov.b64 {%0, %1}, %2;" : "=f"(lo), "=f"(hi) : "l"(v));
}
__device__ __forceinline__ u64 ffma2(u64 a, u64 b, u64 c) {
    u64 d; asm("fma.rn.f32x2 %0, %1, %2, %3;" : "=l"(d) : "l"(a), "l"(b), "l"(c));
    return d;
}

__global__ __launch_bounds__(TPB, 6)
void crumb_kernel(const float* __restrict__ x,
                  const float* __restrict__ mem,
                  float* __restrict__ out,
                  int nblocks)
{
    // Pair-interleaved codebook, row jp (80B stride, 16B aligned):
    //   u64[c] = (-2*m[2jp][c], -2*m[2jp+1][c])  c=0..7
    //   u64[8] = (||m_2jp||^2, ||m_2jp+1||^2)
    __shared__ __align__(16) u64 spair[NJP][10];
    __shared__ float4 sOrig[NCODES][2];

    const int tid = threadIdx.x;

    // ---- setup: scatter codebook into pair-interleaved layout ----
    for (int j = tid; j < NCODES; j += TPB) {
        const float4* m4 = reinterpret_cast<const float4*>(mem);
        float4 a = m4[j * 2 + 0];
        float4 b = m4[j * 2 + 1];
        float mm = a.x*a.x + a.y*a.y + a.z*a.z + a.w*a.w
                 + b.x*b.x + b.y*b.y + b.z*b.z + b.w*b.w;
        float* sp = reinterpret_cast<float*>(&spair[j >> 1][0]);
        int h = j & 1;                    // lo half = even j (first index)
        sp[0*2 + h] = -2.f * a.x;
        sp[1*2 + h] = -2.f * a.y;
        sp[2*2 + h] = -2.f * a.z;
        sp[3*2 + h] = -2.f * a.w;
        sp[4*2 + h] = -2.f * b.x;
        sp[5*2 + h] = -2.f * b.y;
        sp[6*2 + h] = -2.f * b.z;
        sp[7*2 + h] = -2.f * b.w;
        sp[8*2 + h] = mm;
        sOrig[j][0] = a;
        sOrig[j][1] = b;
    }
    __syncthreads();

    const int base = blockIdx.x * (TPB * KPT);
    const float4* x4 = reinterpret_cast<const float4*>(x);

    u64   kp[KPT][8];                       // dup-packed key components
    float bestE[KPT], bestO[KPT];           // running minima: even / odd codes
    int   ipE[KPT],   ipO[KPT];             // winning PAIR index per half

    // ---- load keys (coalesced float4), duplicate into f32x2 halves ----
    #pragma unroll
    for (int p = 0; p < KPT; p++) {
        int b = base + p * TPB + tid;
        int bb = (b < nblocks) ? b : 0;
        float4 a = x4[(size_t)bb * 2 + 0];
        float4 v = x4[(size_t)bb * 2 + 1];
        kp[p][0] = pack2(a.x, a.x);
        kp[p][1] = pack2(a.y, a.y);
        kp[p][2] = pack2(a.z, a.z);
        kp[p][3] = pack2(a.w, a.w);
        kp[p][4] = pack2(v.x, v.x);
        kp[p][5] = pack2(v.y, v.y);
        kp[p][6] = pack2(v.z, v.z);
        kp[p][7] = pack2(v.w, v.w);
        bestE[p] = CUDART_INF_F; bestO[p] = CUDART_INF_F;
        ipE[p] = 0;              ipO[p] = 0;
    }

    // ---- scan code pairs: all loop-carried deps are lat-4 (FMNMX / SEL) ----
    #pragma unroll 4
    for (int jp = 0; jp < NJP; jp++) {
        const ulonglong2* row = reinterpret_cast<const ulonglong2*>(&spair[jp][0]);
        ulonglong2 q0 = row[0];   // c0, c1
        ulonglong2 q1 = row[1];   // c2, c3
        ulonglong2 q2 = row[2];   // c4, c5
        ulonglong2 q3 = row[3];   // c6, c7
        u64 mmp = spair[jp][8];

        #pragma unroll
        for (int p = 0; p < KPT; p++) {
            u64 d = mmp;                      // seed = (mm_j, mm_j+1)
            d = ffma2(kp[p][0], q0.x, d);
            d = ffma2(kp[p][1], q0.y, d);
            d = ffma2(kp[p][2], q1.x, d);
            d = ffma2(kp[p][3], q1.y, d);
            d = ffma2(kp[p][4], q2.x, d);
            d = ffma2(kp[p][5], q2.y, d);
            d = ffma2(kp[p][6], q3.x, d);
            d = ffma2(kp[p][7], q3.y, d);
            float dl, dh; unpack2(d, dl, dh);
            // branchless: FSETP(pred-as-data) + SEL + FMNMX, no guards
            bool tE = dl < bestE[p];
            bool tO = dh < bestO[p];
            ipE[p]   = tE ? jp : ipE[p];
            ipO[p]   = tO ? jp : ipO[p];
            bestE[p] = fminf(bestE[p], dl);
            bestO[p] = fminf(bestO[p], dh);
        }
    }

    // ---- merge halves (even wins ties: first index), gather, store ----
    float4* o4 = reinterpret_cast<float4*>(out);
    #pragma unroll
    for (int p = 0; p < KPT; p++) {
        int b = base + p * TPB + tid;
        if (b < nblocks) {
            // even index = 2*ipE, odd = 2*ipO+1; strict < for odd to win
            int j = (bestO[p] < bestE[p]) ? (2 * ipO[p] + 1) : (2 * ipE[p]);
            o4[(size_t)b * 2 + 0] = sOrig[j][0];
            o4[(size_t)b * 2 + 1] = sOrig[j][1];
        }
    }
}

extern "C" void kernel_launch(void* const* d_in, const int* in_sizes, int n_in,
                              void* d_out, int out_size)
{
    const float* x   = (const float*)d_in[0];
    const float* mem = (const float*)d_in[1];
    float* out = (float*)d_out;

    int nblocks = in_sizes[0] / MBLK;                 // 802816
    int per_cta = TPB * KPT;                          // 512
    int grid = (nblocks + per_cta - 1) / per_cta;     // 1568

    crumb_kernel<<<grid, TPB>>>(x, mem, out, nblocks);
}

// round 8
// speedup vs baseline: 1.6632x; 1.6632x over previous
#include <cuda_runtime.h>
#include <math_constants.h>

// CrumbReconstructor: per 8-float block of x, argmin over 256 codebook rows of
// squared L2, emit the winning row.
//
// score(j) = ||m_j||^2 - 2*k.m_j   (||k||^2 dropped: uniform in j).
//
// f32x2 pairs TWO CODES (j, j+1) per lane-pair. Keys dup-packed once at load;
// codebook smem pair-interleaved (4x LDS.128 + 1x LDS.64 per code pair);
// 8 FFMA2 yield both codes' final scores (seed = (mm_j, mm_j+1)).
//
// R7: keep R4's exact inner-loop ops (its codegen measured fastest) but split
// the running argmin into TWO accumulators by jp parity (A=even jp, B=odd jp).
// The 13-cyc FSETP->guard carried chain per block now advances every OTHER
// iteration, doubling the slack per link without changing the op stream.
// Exact first-index tie-break restored in the epilogue merge.

#define MBLK   8
#define NCODES 256
#define NJP    (NCODES / 2)   // 128 code pairs
#define TPB    128
#define KPT    4              // key-blocks per thread

typedef unsigned long long u64;

__device__ __forceinline__ u64 pack2(float lo, float hi) {
    u64 r; asm("mov.b64 %0, {%1, %2};" : "=l"(r) : "f"(lo), "f"(hi)); return r;
}
__device__ __forceinline__ void unpack2(u64 v, float& lo, float& hi) {
    asm("mov.b64 {%0, %1}, %2;" : "=f"(lo), "=f"(hi) : "l"(v));
}
__device__ __forceinline__ u64 ffma2(u64 a, u64 b, u64 c) {
    u64 d; asm("fma.rn.f32x2 %0, %1, %2, %3;" : "=l"(d) : "l"(a), "l"(b), "l"(c));
    return d;
}

__global__ __launch_bounds__(TPB, 4)
void crumb_kernel(const float* __restrict__ x,
                  const float* __restrict__ mem,
                  float* __restrict__ out,
                  int nblocks)
{
    // Pair-interleaved codebook, row jp (80B stride, 16B aligned):
    //   u64[c] = (-2*m[2jp][c], -2*m[2jp+1][c])  c=0..7
    //   u64[8] = (||m_2jp||^2, ||m_2jp+1||^2)
    __shared__ __align__(16) u64 spair[NJP][10];
    __shared__ float4 sOrig[NCODES][2];

    const int tid = threadIdx.x;

    // ---- setup: scatter codebook into pair-interleaved layout ----
    for (int j = tid; j < NCODES; j += TPB) {
        const float4* m4 = reinterpret_cast<const float4*>(mem);
        float4 a = m4[j * 2 + 0];
        float4 b = m4[j * 2 + 1];
        float mm = a.x*a.x + a.y*a.y + a.z*a.z + a.w*a.w
                 + b.x*b.x + b.y*b.y + b.z*b.z + b.w*b.w;
        float* sp = reinterpret_cast<float*>(&spair[j >> 1][0]);
        int h = j & 1;                    // lo half = even j (first index)
        sp[0*2 + h] = -2.f * a.x;
        sp[1*2 + h] = -2.f * a.y;
        sp[2*2 + h] = -2.f * a.z;
        sp[3*2 + h] = -2.f * a.w;
        sp[4*2 + h] = -2.f * b.x;
        sp[5*2 + h] = -2.f * b.y;
        sp[6*2 + h] = -2.f * b.z;
        sp[7*2 + h] = -2.f * b.w;
        sp[8*2 + h] = mm;
        sOrig[j][0] = a;
        sOrig[j][1] = b;
    }
    __syncthreads();

    const int base = blockIdx.x * (TPB * KPT);
    const float4* x4 = reinterpret_cast<const float4*>(x);

    u64   kp[KPT][8];                  // dup-packed key components
    float bestA[KPT], bestB[KPT];      // parity-split running minima
    int   idxA[KPT],  idxB[KPT];       // winning code index per parity

    // ---- load keys (coalesced float4), duplicate into f32x2 halves ----
    #pragma unroll
    for (int p = 0; p < KPT; p++) {
        int b = base + p * TPB + tid;
        int bb = (b < nblocks) ? b : 0;
        float4 a = x4[(size_t)bb * 2 + 0];
        float4 v = x4[(size_t)bb * 2 + 1];
        kp[p][0] = pack2(a.x, a.x);
        kp[p][1] = pack2(a.y, a.y);
        kp[p][2] = pack2(a.z, a.z);
        kp[p][3] = pack2(a.w, a.w);
        kp[p][4] = pack2(v.x, v.x);
        kp[p][5] = pack2(v.y, v.y);
        kp[p][6] = pack2(v.z, v.z);
        kp[p][7] = pack2(v.w, v.w);
        bestA[p] = CUDART_INF_F; bestB[p] = CUDART_INF_F;
        idxA[p]  = 0;            idxB[p] = 0;
    }

    // ---- scan code pairs, alternating accumulator by jp parity ----
    #pragma unroll 2
    for (int jp2 = 0; jp2 < NJP / 2; jp2++) {
        // ---- even jp -> accumulator A ----
        {
            const int jp = 2 * jp2;
            const ulonglong2* row = reinterpret_cast<const ulonglong2*>(&spair[jp][0]);
            ulonglong2 q0 = row[0];
            ulonglong2 q1 = row[1];
            ulonglong2 q2 = row[2];
            ulonglong2 q3 = row[3];
            u64 mmp = spair[jp][8];
            #pragma unroll
            for (int p = 0; p < KPT; p++) {
                u64 d = mmp;
                d = ffma2(kp[p][0], q0.x, d);
                d = ffma2(kp[p][1], q0.y, d);
                d = ffma2(kp[p][2], q1.x, d);
                d = ffma2(kp[p][3], q1.y, d);
                d = ffma2(kp[p][4], q2.x, d);
                d = ffma2(kp[p][5], q2.y, d);
                d = ffma2(kp[p][6], q3.x, d);
                d = ffma2(kp[p][7], q3.y, d);
                float dl, dh; unpack2(d, dl, dh);
                float m  = fminf(dl, dh);
                int   js = (jp << 1) + ((dl <= dh) ? 0 : 1);
                if (m < bestA[p]) { bestA[p] = m; idxA[p] = js; }
            }
        }
        // ---- odd jp -> accumulator B ----
        {
            const int jp = 2 * jp2 + 1;
            const ulonglong2* row = reinterpret_cast<const ulonglong2*>(&spair[jp][0]);
            ulonglong2 q0 = row[0];
            ulonglong2 q1 = row[1];
            ulonglong2 q2 = row[2];
            ulonglong2 q3 = row[3];
            u64 mmp = spair[jp][8];
            #pragma unroll
            for (int p = 0; p < KPT; p++) {
                u64 d = mmp;
                d = ffma2(kp[p][0], q0.x, d);
                d = ffma2(kp[p][1], q0.y, d);
                d = ffma2(kp[p][2], q1.x, d);
                d = ffma2(kp[p][3], q1.y, d);
                d = ffma2(kp[p][4], q2.x, d);
                d = ffma2(kp[p][5], q2.y, d);
                d = ffma2(kp[p][6], q3.x, d);
                d = ffma2(kp[p][7], q3.y, d);
                float dl, dh; unpack2(d, dl, dh);
                float m  = fminf(dl, dh);
                int   js = (jp << 1) + ((dl <= dh) ? 0 : 1);
                if (m < bestB[p]) { bestB[p] = m; idxB[p] = js; }
            }
        }
    }

    // ---- merge parities (exact first-index tie-break), gather, store ----
    float4* o4 = reinterpret_cast<float4*>(out);
    #pragma unroll
    for (int p = 0; p < KPT; p++) {
        int b = base + p * TPB + tid;
        if (b < nblocks) {
            float bb_ = bestA[p];
            int   jj  = idxA[p];
            if (bestB[p] < bb_ || (bestB[p] == bb_ && idxB[p] < jj)) {
                bb_ = bestB[p]; jj = idxB[p];
            }
            o4[(size_t)b * 2 + 0] = sOrig[jj][0];
            o4[(size_t)b * 2 + 1] = sOrig[jj][1];
        }
    }
}

extern "C" void kernel_launch(void* const* d_in, const int* in_sizes, int n_in,
                              void* d_out, int out_size)
{
    const float* x   = (const float*)d_in[0];
    const float* mem = (const float*)d_in[1];
    float* out = (float*)d_out;

    int nblocks = in_sizes[0] / MBLK;                 // 802816
    int per_cta = TPB * KPT;                          // 512
    int grid = (nblocks + per_cta - 1) / per_cta;     // 1568

    crumb_kernel<<<grid, TPB>>>(x, mem, out, nblocks);
}

// round 9
// speedup vs baseline: 1.9261x; 1.1580x over previous
#include <cuda_runtime.h>
#include <math_constants.h>

// CrumbReconstructor: per 8-float block of x, argmin over 256 codebook rows of
// squared L2, emit the winning row.
//
// score(j) = ||m_j||^2 - 2*k.m_j   (||k||^2 dropped: uniform in j).
// f32x2 pairs TWO CODES (j, j+1) per lane-pair; 8 FFMA2 per code pair.
//
// R8: hierarchical argmin. Measured: >half of all issue slots were argmin
// bookkeeping. Inner loop now tracks only a running MIN per group of 8 codes
// (1 FMNMX per pair, zero compares/selects); one guarded update per group of
// 8; the winning code index is recovered per block by recomputing the winning
// group's 8 scores (bitwise-identical FFMA2s) and taking the first equal --
// exact first-index argmin semantics.

#define MBLK   8
#define NCODES 256
#define NJP    (NCODES / 2)   // 128 code pairs
#define NGRP   (NJP / 4)      // 32 groups of 4 pairs (8 codes)
#define TPB    128
#define KPT    4              // key-blocks per thread

typedef unsigned long long u64;

__device__ __forceinline__ u64 pack2(float lo, float hi) {
    u64 r; asm("mov.b64 %0, {%1, %2};" : "=l"(r) : "f"(lo), "f"(hi)); return r;
}
__device__ __forceinline__ void unpack2(u64 v, float& lo, float& hi) {
    asm("mov.b64 {%0, %1}, %2;" : "=f"(lo), "=f"(hi) : "l"(v));
}
__device__ __forceinline__ u64 ffma2(u64 a, u64 b, u64 c) {
    u64 d; asm("fma.rn.f32x2 %0, %1, %2, %3;" : "=l"(d) : "l"(a), "l"(b), "l"(c));
    return d;
}

__global__ __launch_bounds__(TPB, 4)
void crumb_kernel(const float* __restrict__ x,
                  const float* __restrict__ mem,
                  float* __restrict__ out,
                  int nblocks)
{
    // Pair-interleaved codebook, row jp (80B stride, 16B aligned):
    //   u64[c] = (-2*m[2jp][c], -2*m[2jp+1][c])  c=0..7
    //   u64[8] = (||m_2jp||^2, ||m_2jp+1||^2)
    __shared__ __align__(16) u64 spair[NJP][10];
    __shared__ float4 sOrig[NCODES][2];

    const int tid = threadIdx.x;

    // ---- setup: scatter codebook into pair-interleaved layout ----
    for (int j = tid; j < NCODES; j += TPB) {
        const float4* m4 = reinterpret_cast<const float4*>(mem);
        float4 a = m4[j * 2 + 0];
        float4 b = m4[j * 2 + 1];
        float mm = a.x*a.x + a.y*a.y + a.z*a.z + a.w*a.w
                 + b.x*b.x + b.y*b.y + b.z*b.z + b.w*b.w;
        float* sp = reinterpret_cast<float*>(&spair[j >> 1][0]);
        int h = j & 1;                    // lo half = even j (first index)
        sp[0*2 + h] = -2.f * a.x;
        sp[1*2 + h] = -2.f * a.y;
        sp[2*2 + h] = -2.f * a.z;
        sp[3*2 + h] = -2.f * a.w;
        sp[4*2 + h] = -2.f * b.x;
        sp[5*2 + h] = -2.f * b.y;
        sp[6*2 + h] = -2.f * b.z;
        sp[7*2 + h] = -2.f * b.w;
        sp[8*2 + h] = mm;
        sOrig[j][0] = a;
        sOrig[j][1] = b;
    }
    __syncthreads();

    const int base = blockIdx.x * (TPB * KPT);
    const float4* x4 = reinterpret_cast<const float4*>(x);

    u64   kp[KPT][8];              // dup-packed key components
    float gbest[KPT];              // global running min per block
    int   gidx[KPT];               // winning GROUP (8 codes) per block

    // ---- load keys (coalesced float4), duplicate into f32x2 halves ----
    #pragma unroll
    for (int p = 0; p < KPT; p++) {
        int b = base + p * TPB + tid;
        int bb = (b < nblocks) ? b : 0;
        float4 a = x4[(size_t)bb * 2 + 0];
        float4 v = x4[(size_t)bb * 2 + 1];
        kp[p][0] = pack2(a.x, a.x);
        kp[p][1] = pack2(a.y, a.y);
        kp[p][2] = pack2(a.z, a.z);
        kp[p][3] = pack2(a.w, a.w);
        kp[p][4] = pack2(v.x, v.x);
        kp[p][5] = pack2(v.y, v.y);
        kp[p][6] = pack2(v.z, v.z);
        kp[p][7] = pack2(v.w, v.w);
        gbest[p] = CUDART_INF_F;
        gidx[p]  = 0;
    }

    // ---- scan groups of 4 pairs: inner path is pure FFMA2 + FMNMX ----
    #pragma unroll 2
    for (int g = 0; g < NGRP; g++) {
        float t[KPT];                      // group-running min per block
        #pragma unroll
        for (int q = 0; q < 4; q++) {
            const int jp = g * 4 + q;
            const ulonglong2* row = reinterpret_cast<const ulonglong2*>(&spair[jp][0]);
            ulonglong2 q0 = row[0];
            ulonglong2 q1 = row[1];
            ulonglong2 q2 = row[2];
            ulonglong2 q3 = row[3];
            u64 mmp = spair[jp][8];
            #pragma unroll
            for (int p = 0; p < KPT; p++) {
                u64 d = mmp;               // seed = (mm_j, mm_j+1)
                d = ffma2(kp[p][0], q0.x, d);
                d = ffma2(kp[p][1], q0.y, d);
                d = ffma2(kp[p][2], q1.x, d);
                d = ffma2(kp[p][3], q1.y, d);
                d = ffma2(kp[p][4], q2.x, d);
                d = ffma2(kp[p][5], q2.y, d);
                d = ffma2(kp[p][6], q3.x, d);
                d = ffma2(kp[p][7], q3.y, d);
                float dl, dh; unpack2(d, dl, dh);
                float m = fminf(dl, dh);
                t[p] = (q == 0) ? m : fminf(t[p], m);
            }
        }
        // one guarded update per group of 8 codes; strict < keeps first group
        #pragma unroll
        for (int p = 0; p < KPT; p++) {
            if (t[p] < gbest[p]) { gbest[p] = t[p]; gidx[p] = g; }
        }
    }

    // ---- per block: recover exact first index within the winning group ----
    float4* o4 = reinterpret_cast<float4*>(out);
    #pragma unroll
    for (int p = 0; p < KPT; p++) {
        int b = base + p * TPB + tid;
        if (b >= nblocks) continue;
        const int g = gidx[p];
        const float v = gbest[p];
        int jwin = 0;
        bool found = false;
        #pragma unroll
        for (int q = 0; q < 4; q++) {
            if (found) continue;
            const int jp = g * 4 + q;
            const ulonglong2* row = reinterpret_cast<const ulonglong2*>(&spair[jp][0]);
            ulonglong2 q0 = row[0];
            ulonglong2 q1 = row[1];
            ulonglong2 q2 = row[2];
            ulonglong2 q3 = row[3];
            u64 d = spair[jp][8];
            d = ffma2(kp[p][0], q0.x, d);
            d = ffma2(kp[p][1], q0.y, d);
            d = ffma2(kp[p][2], q1.x, d);
            d = ffma2(kp[p][3], q1.y, d);
            d = ffma2(kp[p][4], q2.x, d);
            d = ffma2(kp[p][5], q2.y, d);
            d = ffma2(kp[p][6], q3.x, d);
            d = ffma2(kp[p][7], q3.y, d);
            float dl, dh; unpack2(d, dl, dh);
            if (dl == v)      { jwin = (jp << 1);     found = true; }
            else if (dh == v) { jwin = (jp << 1) + 1; found = true; }
        }
        o4[(size_t)b * 2 + 0] = sOrig[jwin][0];
        o4[(size_t)b * 2 + 1] = sOrig[jwin][1];
    }
}

extern "C" void kernel_launch(void* const* d_in, const int* in_sizes, int n_in,
                              void* d_out, int out_size)
{
    const float* x   = (const float*)d_in[0];
    const float* mem = (const float*)d_in[1];
    float* out = (float*)d_out;

    int nblocks = in_sizes[0] / MBLK;                 // 802816
    int per_cta = TPB * KPT;                          // 512
    int grid = (nblocks + per_cta - 1) / per_cta;     // 1568

    crumb_kernel<<<grid, TPB>>>(x, mem, out, nblocks);
}